// round 12
// baseline (speedup 1.0000x reference)
#include <cuda_runtime.h>
#include <cuda_bf16.h>
#include <cstdint>

// Problem constants (shape fixed by dataset: img [64, 3, 512, 512])
constexpr int NCH = 192;           // 64*3 channels
constexpr int P   = 262144;        // 512*512 pixels / channel
constexpr int NB  = 256;           // bins

// Pipeline structure (R7 topology: the validated-fast configuration)
constexpr int GROUPS = 8;
constexpr int CPG    = NCH / GROUPS;   // 24 channels per group
constexpr int HPC    = 8;              // hist blocks per channel
constexpr int APC    = 16;             // apply blocks per channel
constexpr int NHIST  = CPG * HPC;      // 192
constexpr int NAPPLY = CPG * APC;      // 384
constexpr int NBLK   = NHIST + NAPPLY; // 576 <= 148*4 -> fully co-resident

// Scratch — __device__ globals.
// g_part: per-slice partial histograms, PLAIN STORES (overwritten every run,
//         so no cross-replay zeroing needed, no global atomics).
// g_u8:   packed 1-byte pixel values; written by hist(g), read by apply(g)
//         moments later -> L2-resident handoff, removes apply's float re-read.
// g_ctr/g_adone: reset in-kernel by the last apply block per group.
__device__ int           g_part[NCH * HPC * NB];     // 1.57 MB
__device__ unsigned char g_u8[(size_t)NCH * P];      // 50.3 MB
__device__ int           g_ctr  [GROUPS];
__device__ int           g_adone[GROUPS];

// ---------------------------------------------------------------------------
// Fused persistent kernel (R7 sync topology, verbatim):
//  - 192 hist blocks (read-bound): stream float input once (__ldcs: dead
//    after), write packed u8 scratch, per-warp smem hists -> plain-store
//    partials, bump group counter.
//  - 384 apply blocks (write-bound): spin on group counter, build LUT locally
//    from the 8 partials (exact PIL math), read u8 scratch (L2 hits),
//    translate + __stcs-write output.
// DRAM traffic: 201MB in + ~50MB scratch writeback + 201MB out ~= 452MB.
// ---------------------------------------------------------------------------
__global__ void __launch_bounds__(256, 4) fused_kernel(const float* __restrict__ in,
                                                       float* __restrict__ out) {
    __shared__ int sh[8 * NB];     // hist: 8 per-warp hists. apply: H/CS/RED/LUT.
    const int tid = threadIdx.x;
    const int bid = blockIdx.x;

    if (bid < NHIST) {
        // ---------------- HIST ROLE ----------------
        const int cg = bid / HPC;          // channel within group
        const int h  = bid % HPC;          // slice within channel
        int* const myh = &sh[(tid >> 5) * NB];

        for (int g = 0; g < GROUPS; g++) {
            const int c = g * CPG + cg;
            for (int i = tid; i < 8 * NB; i += 256) sh[i] = 0;
            __syncthreads();

            const float4* bi =
                reinterpret_cast<const float4*>(in + (size_t)c * P) + h * (P / 4 / HPC);
            unsigned int* bo =
                reinterpret_cast<unsigned int*>(g_u8 + (size_t)c * P) + h * (P / 4 / HPC);
            for (int i = tid; i < P / 4 / HPC; i += 512) {   // 8192 uint/slice
                float4 a = __ldcs(&bi[i]);         // input dead after this read
                float4 b = __ldcs(&bi[i + 256]);
                int a0 = (int)a.x, a1 = (int)a.y, a2 = (int)a.z, a3 = (int)a.w;
                int b0 = (int)b.x, b1 = (int)b.y, b2 = (int)b.z, b3 = (int)b.w;
                bo[i] = (unsigned)a0 | ((unsigned)a1 << 8) |
                        ((unsigned)a2 << 16) | ((unsigned)a3 << 24);
                bo[i + 256] = (unsigned)b0 | ((unsigned)b1 << 8) |
                              ((unsigned)b2 << 16) | ((unsigned)b3 << 24);
                atomicAdd(&myh[a0], 1);
                atomicAdd(&myh[a1], 1);
                atomicAdd(&myh[a2], 1);
                atomicAdd(&myh[a3], 1);
                atomicAdd(&myh[b0], 1);
                atomicAdd(&myh[b1], 1);
                atomicAdd(&myh[b2], 1);
                atomicAdd(&myh[b3], 1);
            }
            __syncthreads();

            // Reduce 8 warp-hists -> plain store of this slice's partial.
            int s = 0;
#pragma unroll
            for (int k = 0; k < 8; k++) s += sh[k * NB + tid];
            g_part[(c * HPC + h) * NB + tid] = s;

            __threadfence();               // release partial + scratch bytes
            __syncthreads();               // all threads' stores+fences done
            if (tid == 0) atomicAdd(&g_ctr[g], 1);
        }
    } else {
        // ---------------- APPLY ROLE ----------------
        const int a  = bid - NHIST;
        const int cg = a / APC;            // channel within group
        const int j  = a % APC;            // slice within channel
        int*   H   = sh;
        int*   CS  = sh + NB;
        int*   RED = sh + 2 * NB;
        float* LUT = reinterpret_cast<float*>(sh + 3 * NB);
        __shared__ int s_ticket;

        for (int g = 0; g < GROUPS; g++) {
            const int c = g * CPG + cg;

            // Wait until all hist blocks of this group have published.
            if (tid == 0) {
                while (*(volatile int*)&g_ctr[g] < NHIST) __nanosleep(128);
                s_ticket = atomicAdd(&g_adone[g], 1);
            }
            __syncthreads();
            __threadfence();
            // Last apply block past the spin (counters final) resets group
            // state for the next graph replay.
            if (s_ticket == NAPPLY - 1 && tid == 0) {
                g_adone[g] = 0;
                g_ctr[g]   = 0;
            }

            // Build this channel's LUT locally (exact PIL integer math).
            int hv = 0;
#pragma unroll
            for (int k = 0; k < HPC; k++)
                hv += __ldcg(&g_part[(c * HPC + k) * NB + tid]);
            H[tid]  = hv;
            CS[tid] = hv;
            __syncthreads();
#pragma unroll
            for (int off = 1; off < NB; off <<= 1) {       // inclusive scan
                int v = (tid >= off) ? CS[tid - off] : 0;
                __syncthreads();
                CS[tid] += v;
                __syncthreads();
            }
            RED[tid] = hv ? tid : -1;                      // last nonzero bin
            __syncthreads();
#pragma unroll
            for (int sdx = 128; sdx > 0; sdx >>= 1) {
                if (tid < sdx) RED[tid] = max(RED[tid], RED[tid + sdx]);
                __syncthreads();
            }
            const int last_val = H[RED[0]];
            const int step = (P - last_val) / 255;
            const int safe = step > 0 ? step : 1;
            const int prev = tid ? CS[tid - 1] : 0;
            int lv = (prev + step / 2) / safe;
            lv = min(max(lv, 0), 255);
            if (step == 0) lv = tid;       // passthrough as identity LUT
            LUT[tid] = (float)lv;
            __syncthreads();

            // Apply this block's slice from u8 scratch (L2-hot):
            // 1024 uint4, 2 in flight; each uint4 -> 4 float4 stores.
            const uint4* bi =
                reinterpret_cast<const uint4*>(g_u8 + (size_t)c * P) + j * (P / 16 / APC);
            float4* bo =
                reinterpret_cast<float4*>(out + (size_t)c * P) + j * (P / 4 / APC);
            for (int i = tid; i < P / 16 / APC; i += 512) {
                uint4 x = __ldcs(&bi[i]);          // scratch dead after read
                uint4 y = __ldcs(&bi[i + 256]);
                float4 o;
                int ob = i * 4;
                o.x = LUT[ x.x        & 255]; o.y = LUT[(x.x >>  8) & 255];
                o.z = LUT[(x.x >> 16) & 255]; o.w = LUT[(x.x >> 24)      ];
                __stcs(&bo[ob + 0], o);
                o.x = LUT[ x.y        & 255]; o.y = LUT[(x.y >>  8) & 255];
                o.z = LUT[(x.y >> 16) & 255]; o.w = LUT[(x.y >> 24)      ];
                __stcs(&bo[ob + 1], o);
                o.x = LUT[ x.z        & 255]; o.y = LUT[(x.z >>  8) & 255];
                o.z = LUT[(x.z >> 16) & 255]; o.w = LUT[(x.z >> 24)      ];
                __stcs(&bo[ob + 2], o);
                o.x = LUT[ x.w        & 255]; o.y = LUT[(x.w >>  8) & 255];
                o.z = LUT[(x.w >> 16) & 255]; o.w = LUT[(x.w >> 24)      ];
                __stcs(&bo[ob + 3], o);
                ob = (i + 256) * 4;
                o.x = LUT[ y.x        & 255]; o.y = LUT[(y.x >>  8) & 255];
                o.z = LUT[(y.x >> 16) & 255]; o.w = LUT[(y.x >> 24)      ];
                __stcs(&bo[ob + 0], o);
                o.x = LUT[ y.y        & 255]; o.y = LUT[(y.y >>  8) & 255];
                o.z = LUT[(y.y >> 16) & 255]; o.w = LUT[(y.y >> 24)      ];
                __stcs(&bo[ob + 1], o);
                o.x = LUT[ y.z        & 255]; o.y = LUT[(y.z >>  8) & 255];
                o.z = LUT[(y.z >> 16) & 255]; o.w = LUT[(y.z >> 24)      ];
                __stcs(&bo[ob + 2], o);
                o.x = LUT[ y.w        & 255]; o.y = LUT[(y.w >>  8) & 255];
                o.z = LUT[(y.w >> 16) & 255]; o.w = LUT[(y.w >> 24)      ];
                __stcs(&bo[ob + 3], o);
            }
            __syncthreads();               // smem reuse next group
        }
    }
}

// ---------------------------------------------------------------------------
extern "C" void kernel_launch(void* const* d_in, const int* in_sizes, int n_in,
                              void* d_out, int out_size) {
    const float* img = (const float*)d_in[0];
    float* out = (float*)d_out;
    fused_kernel<<<NBLK, 256>>>(img, out);
}

// round 13
// speedup vs baseline: 1.4927x; 1.4927x over previous
#include <cuda_runtime.h>
#include <cuda_bf16.h>
#include <cstdint>

// Problem constants (shape fixed by dataset: img [64, 3, 512, 512])
constexpr int NCH = 192;           // 64*3 channels
constexpr int P   = 262144;        // 512*512 pixels / channel
constexpr int NB  = 256;           // bins

// Pipeline structure (identical topology to the 93.8us R7 kernel)
constexpr int GROUPS = 8;
constexpr int CPG    = NCH / GROUPS;   // 24 channels per group
constexpr int HPC    = 8;              // hist blocks per channel
constexpr int APC    = 16;             // apply blocks per channel
constexpr int NHIST  = CPG * HPC;      // 192
constexpr int NAPPLY = CPG * APC;      // 384
constexpr int NBLK   = NHIST + NAPPLY; // 576 <= 148*4 -> fully co-resident

// Scratch — __device__ globals.
// g_part: per-slice partial histograms written with PLAIN STORES. They are
//         fully overwritten every run, so no cross-replay zeroing is needed.
// g_ctr/g_adone: group release/progress counters; reset by a tiny trailing
//         kernel (16 ints).
__device__ int g_part [NCH * HPC * NB];   // 1.57 MB, L2-resident during handoff
__device__ int g_ctr  [GROUPS];
__device__ int g_adone[GROUPS];           // kept for ABI parity; unused waits

// ---------------------------------------------------------------------------
// Fused persistent kernel (R7 structure):
//  - 192 hist blocks (read-bound): per-warp smem hists -> plain-store partial
//    per (channel, slice), bump group counter.
//  - 384 apply blocks (write-bound): spin on group counter, build LUT locally
//    from the 8 partials (exact PIL math), translate + __stcs-write slice.
// ---------------------------------------------------------------------------
__global__ void __launch_bounds__(256, 4) fused_kernel(const float* __restrict__ in,
                                                       float* __restrict__ out) {
    __shared__ int sh[8 * NB];     // hist: 8 per-warp hists. apply: H/CS/RED/LUT.
    const int tid = threadIdx.x;
    const int bid = blockIdx.x;

    if (bid < NHIST) {
        // ---------------- HIST ROLE (R7, atomics -> plain partial store) ----
        const int cg = bid / HPC;          // channel within group
        const int h  = bid % HPC;          // slice within channel
        int* const myh = &sh[(tid >> 5) * NB];

        for (int g = 0; g < GROUPS; g++) {
            const int c = g * CPG + cg;
            for (int i = tid; i < 8 * NB; i += 256) sh[i] = 0;
            __syncthreads();

            const float4* bi =
                reinterpret_cast<const float4*>(in + (size_t)c * P) + h * (P / 4 / HPC);
            for (int i = tid; i < P / 4 / HPC; i += 512) {   // 8192 float4 / slice
                float4 a = bi[i];
                float4 b = bi[i + 256];
                atomicAdd(&myh[(int)a.x], 1);
                atomicAdd(&myh[(int)a.y], 1);
                atomicAdd(&myh[(int)a.z], 1);
                atomicAdd(&myh[(int)a.w], 1);
                atomicAdd(&myh[(int)b.x], 1);
                atomicAdd(&myh[(int)b.y], 1);
                atomicAdd(&myh[(int)b.z], 1);
                atomicAdd(&myh[(int)b.w], 1);
            }
            __syncthreads();

            // Reduce 8 warp-hists -> plain store of this slice's partial.
            int s = 0;
#pragma unroll
            for (int k = 0; k < 8; k++) s += sh[k * NB + tid];
            g_part[(c * HPC + h) * NB + tid] = s;

            __threadfence();               // release my partial before counting
            __syncthreads();               // all threads' stores+fences done
            if (tid == 0) atomicAdd(&g_ctr[g], 1);
        }
    } else {
        // ---------------- APPLY ROLE (R7, hist load -> partial sum) --------
        const int a  = bid - NHIST;
        const int cg = a / APC;            // channel within group
        const int j  = a % APC;            // slice within channel
        int*   H   = sh;
        int*   CS  = sh + NB;
        int*   RED = sh + 2 * NB;
        float* LUT = reinterpret_cast<float*>(sh + 3 * NB);

        for (int g = 0; g < GROUPS; g++) {
            const int c = g * CPG + cg;

            // Wait until all hist blocks of this group have published.
            if (tid == 0) {
                while (*(volatile int*)&g_ctr[g] < NHIST) __nanosleep(128);
            }
            __syncthreads();
            __threadfence();

            // Build this channel's LUT locally (exact PIL integer math).
            int hv = 0;
#pragma unroll
            for (int k = 0; k < HPC; k++)
                hv += __ldcg(&g_part[(c * HPC + k) * NB + tid]);
            H[tid]  = hv;
            CS[tid] = hv;
            __syncthreads();
#pragma unroll
            for (int off = 1; off < NB; off <<= 1) {       // inclusive scan
                int v = (tid >= off) ? CS[tid - off] : 0;
                __syncthreads();
                CS[tid] += v;
                __syncthreads();
            }
            RED[tid] = hv ? tid : -1;                      // last nonzero bin
            __syncthreads();
#pragma unroll
            for (int sdx = 128; sdx > 0; sdx >>= 1) {
                if (tid < sdx) RED[tid] = max(RED[tid], RED[tid + sdx]);
                __syncthreads();
            }
            const int last_val = H[RED[0]];
            const int step = (P - last_val) / 255;
            const int safe = step > 0 ? step : 1;
            const int prev = tid ? CS[tid - 1] : 0;
            int lv = (prev + step / 2) / safe;
            lv = min(max(lv, 0), 255);
            if (step == 0) lv = tid;       // passthrough as identity LUT
            LUT[tid] = (float)lv;
            __syncthreads();

            // Apply this block's slice: 4096 float4, 2 loads in flight.
            const float4* bi =
                reinterpret_cast<const float4*>(in + (size_t)c * P) + j * (P / 4 / APC);
            float4* bo =
                reinterpret_cast<float4*>(out + (size_t)c * P) + j * (P / 4 / APC);
            for (int i = tid; i < P / 4 / APC; i += 512) {
                float4 x = bi[i];
                float4 y = bi[i + 256];
                float4 ox, oy;
                ox.x = LUT[(int)x.x]; ox.y = LUT[(int)x.y];
                ox.z = LUT[(int)x.z]; ox.w = LUT[(int)x.w];
                oy.x = LUT[(int)y.x]; oy.y = LUT[(int)y.y];
                oy.z = LUT[(int)y.z]; oy.w = LUT[(int)y.w];
                __stcs(&bo[i], ox);            // evict-first writes: protect L2
                __stcs(&bo[i + 256], oy);      // residency of upcoming input
            }
            __syncthreads();                    // smem reuse next group
        }
    }
}

// ---------------------------------------------------------------------------
// Tiny cleanup: reset the 16 group counters so the next graph replay starts
// clean. (Partial histograms need no reset — plain-store overwritten.)
// ---------------------------------------------------------------------------
__global__ void cleanup_kernel() {
    if (threadIdx.x < GROUPS) {
        g_ctr  [threadIdx.x] = 0;
        g_adone[threadIdx.x] = 0;
    }
}

// ---------------------------------------------------------------------------
extern "C" void kernel_launch(void* const* d_in, const int* in_sizes, int n_in,
                              void* d_out, int out_size) {
    const float* img = (const float*)d_in[0];
    float* out = (float*)d_out;

    fused_kernel<<<NBLK, 256>>>(img, out);
    cleanup_kernel<<<1, 32>>>();
}